// round 8
// baseline (speedup 1.0000x reference)
#include <cuda_runtime.h>
#include <cuda_bf16.h>
#include <cstdint>

#define B_ 8192
#define M_ 256
#define N_ 512
#define NITER_ 16

// ---------------- device scratch (no allocation allowed) --------------------
__device__ __align__(128) __nv_bfloat16 g_yh[(size_t)B_ * M_], g_yl[(size_t)B_ * M_];
__device__ __align__(128) __nv_bfloat16 g_Wh[N_ * M_], g_Wl[N_ * M_];
__device__ __align__(128) __nv_bfloat16 g_Dh[N_ * N_], g_Dl[N_ * N_];
__device__ __align__(128) __nv_bfloat16 g_Sth[N_ * N_], g_Stl[N_ * N_];
__device__ __align__(128) __nv_bfloat16 g_Dth[N_ * N_], g_Dtl[N_ * N_];
__device__ __align__(128) __nv_bfloat16 g_Eh[N_ * N_], g_El[N_ * N_];
__device__ __align__(128) __nv_bfloat16 g_Wyh[(size_t)B_ * N_], g_Wyl[(size_t)B_ * N_];
__device__ __align__(128) __nv_bfloat16 g_dh[(size_t)B_ * N_], g_dl[(size_t)B_ * N_];
__device__ __align__(128) __nv_bfloat16 g_Ph[(size_t)B_ * N_], g_Pl[(size_t)B_ * N_];
__device__ __align__(128) float g_Vf[(size_t)B_ * N_];

// ---------------- PTX helpers (compute_103 baseline ISA only) ---------------
__device__ __forceinline__ uint32_t smem_u32(const void* p) {
    uint32_t a;
    asm("{ .reg .u64 t; cvta.to.shared.u64 t, %1; cvt.u32.u64 %0, t; }"
        : "=r"(a) : "l"(p));
    return a;
}

__device__ __forceinline__ void cp16(uint32_t saddr, const void* gaddr) {
    asm volatile("cp.async.cg.shared.global [%0], [%1], 16;"
                 :: "r"(saddr), "l"(gaddr));
}
__device__ __forceinline__ void cp_commit() {
    asm volatile("cp.async.commit_group;");
}
template <int N>
__device__ __forceinline__ void cp_wait() {
    asm volatile("cp.async.wait_group %0;" :: "n"(N));
}

__device__ __forceinline__ uint4 ldsm_x4(uint32_t addr) {
    uint4 r;
    asm volatile("ldmatrix.sync.aligned.m8n8.x4.shared.b16 {%0,%1,%2,%3}, [%4];"
                 : "=r"(r.x), "=r"(r.y), "=r"(r.z), "=r"(r.w) : "r"(addr));
    return r;
}

__device__ __forceinline__ void mma_bf16(float* c, uint4 a, uint32_t b0, uint32_t b1) {
    asm volatile(
        "mma.sync.aligned.m16n8k16.row.col.f32.bf16.bf16.f32 "
        "{%0,%1,%2,%3}, {%4,%5,%6,%7}, {%8,%9}, {%0,%1,%2,%3};"
        : "+f"(c[0]), "+f"(c[1]), "+f"(c[2]), "+f"(c[3])
        : "r"(a.x), "r"(a.y), "r"(a.z), "r"(a.w), "r"(b0), "r"(b1));
}

__device__ __forceinline__ float soft_thr_f(float u, float t) {
    return fmaxf(u - t, 0.f) - fmaxf(-u - t, 0.f);
}

// ---------------- prologue / elementwise kernels ----------------------------
__global__ void split_mat(const float* __restrict__ in,
                          __nv_bfloat16* __restrict__ hi,
                          __nv_bfloat16* __restrict__ lo, int n) {
    int i = (blockIdx.x * blockDim.x + threadIdx.x) * 4;
    if (i >= n) return;
    float4 v = *(const float4*)(in + i);
    float x[4] = {v.x, v.y, v.z, v.w};
    __nv_bfloat16 h[4], l[4];
    #pragma unroll
    for (int j = 0; j < 4; j++) {
        h[j] = __float2bfloat16(x[j]);
        l[j] = __float2bfloat16(x[j] - __bfloat162float(h[j]));
    }
    *(__nv_bfloat162*)(hi + i)     = __nv_bfloat162(h[0], h[1]);
    *(__nv_bfloat162*)(hi + i + 2) = __nv_bfloat162(h[2], h[3]);
    *(__nv_bfloat162*)(lo + i)     = __nv_bfloat162(l[0], l[1]);
    *(__nv_bfloat162*)(lo + i + 2) = __nv_bfloat162(l[2], l[3]);
}

// P0 = soft_thr(V) split  (d0 = 0 makes the first gemm1 trivial)
__global__ void thr_split(const float* __restrict__ V,
                          __nv_bfloat16* __restrict__ hi,
                          __nv_bfloat16* __restrict__ lo,
                          const float* __restrict__ thr, int n) {
    int i = (blockIdx.x * blockDim.x + threadIdx.x) * 4;
    if (i >= n) return;
    float theta = __ldg(thr);
    float4 v = *(const float4*)(V + i);
    float x[4] = {v.x, v.y, v.z, v.w};
    __nv_bfloat16 h[4], l[4];
    #pragma unroll
    for (int j = 0; j < 4; j++) {
        float a = soft_thr_f(x[j], theta);
        h[j] = __float2bfloat16(a);
        l[j] = __float2bfloat16(a - __bfloat162float(h[j]));
    }
    *(__nv_bfloat162*)(hi + i)     = __nv_bfloat162(h[0], h[1]);
    *(__nv_bfloat162*)(hi + i + 2) = __nv_bfloat162(h[2], h[3]);
    *(__nv_bfloat162*)(lo + i)     = __nv_bfloat162(l[0], l[1]);
    *(__nv_bfloat162*)(lo + i + 2) = __nv_bfloat162(l[2], l[3]);
}

// out = in^T for 512x512, emitting bf16 hi/lo split
__global__ void transpose_split512(const float* __restrict__ in,
                                   __nv_bfloat16* __restrict__ hi,
                                   __nv_bfloat16* __restrict__ lo) {
    __shared__ float tile[32][33];
    int x = blockIdx.x * 32 + threadIdx.x;
    int y0 = blockIdx.y * 32;
    #pragma unroll
    for (int j = threadIdx.y; j < 32; j += 8)
        tile[j][threadIdx.x] = in[(size_t)(y0 + j) * N_ + x];
    __syncthreads();
    int xo = blockIdx.y * 32 + threadIdx.x;
    int yo0 = blockIdx.x * 32;
    #pragma unroll
    for (int j = threadIdx.y; j < 32; j += 8) {
        float v = tile[threadIdx.x][j];
        __nv_bfloat16 h = __float2bfloat16(v);
        __nv_bfloat16 l = __float2bfloat16(v - __bfloat162float(h));
        size_t o = (size_t)(yo0 + j) * N_ + xo;
        hi[o] = h;
        lo[o] = l;
    }
}

// ---------------- split-bf16 tensor-core GEMM (mma.sync) --------------------
// C[Mr x Ncols] = A @ Bm^T; A,Bm given as bf16 hi/lo splits.
// 3-term: ah*bh + al*bh + ah*bl. CTA tile 128x128, 8 warps (2x4 -> 64x32),
// K-chunk 32, 3-stage cp.async pipeline, 2 CTAs/SM.
// SMEM stage layout: region A (16KB): 128 rows x 128B, row = [AH(4x16B)|AL(4x16B)],
// unit swizzle u^(row&7); region B (16KB) identical. Stage = 32KB, 3 stages.
static constexpr int STG = 32768;
static constexpr int OFF_B = 16384;
static constexpr int SMEM_TOTAL = 3 * STG;  // 98304

template <bool ADD_V, bool SOFT, bool WF32, bool WSPLIT>
__global__ __launch_bounds__(256, 2)
void gemm_tc(const __nv_bfloat16* __restrict__ Ah, const __nv_bfloat16* __restrict__ Al,
             const __nv_bfloat16* __restrict__ Bh, const __nv_bfloat16* __restrict__ Bl,
             const float* __restrict__ Vadd, float* __restrict__ Cf,
             __nv_bfloat16* __restrict__ Chi, __nv_bfloat16* __restrict__ Clo,
             int K, int Ncols, const float* __restrict__ thr) {
    extern __shared__ char sm[];
    const uint32_t sbase = smem_u32(sm);

    const int tid = threadIdx.x;
    const int lane = tid & 31;
    const int wid = tid >> 5;
    const int warp_m = wid & 1;    // 0..1
    const int warp_n = wid >> 1;   // 0..3
    const int bx = blockIdx.x, by = blockIdx.y;
    const int rowA0 = by * 128;
    const int rowB0 = bx * 128;

    // cp.async mapping: 2048 16B-units per chunk, 8 per thread.
    // i-th issue: mat = i>>1 (0:AH 1:AL 2:BH 3:BL), r = (i&1)*64 + tid>>2, u4 = tid&3
#define ISSUE_CHUNK(kt_, s_)                                                   \
    do {                                                                       \
        const uint32_t stb_ = sbase + (uint32_t)(s_)*STG;                      \
        _Pragma("unroll")                                                      \
        for (int i_ = 0; i_ < 8; i_++) {                                       \
            const int mat_ = i_ >> 1;                                          \
            const int r_ = (i_ & 1) * 64 + (tid >> 2);                         \
            const int u4_ = tid & 3;                                           \
            const int unit_ = u4_ + (mat_ & 1) * 4;                            \
            const uint32_t reg_ = (mat_ >= 2) ? OFF_B : 0;                     \
            uint32_t dst_ = stb_ + reg_ + r_ * 128 + ((unit_ ^ (r_ & 7)) << 4);\
            const __nv_bfloat16* src_;                                         \
            if (mat_ == 0)      src_ = Ah + (size_t)(rowA0 + r_) * K;          \
            else if (mat_ == 1) src_ = Al + (size_t)(rowA0 + r_) * K;          \
            else if (mat_ == 2) src_ = Bh + (size_t)(rowB0 + r_) * K;          \
            else                src_ = Bl + (size_t)(rowB0 + r_) * K;          \
            cp16(dst_, src_ + (kt_) * 32 + u4_ * 8);                           \
        }                                                                      \
        cp_commit();                                                           \
    } while (0)

    float acc[4][4][4];
    #pragma unroll
    for (int a = 0; a < 4; a++)
        #pragma unroll
        for (int b = 0; b < 4; b++)
            #pragma unroll
            for (int c = 0; c < 4; c++) acc[a][b][c] = 0.f;

    // ldmatrix per-thread constants
    const int rA = lane & 15;
    const int khA = lane >> 4;
    const int sxA = rA & 7;
    const int rB = ((lane >> 4) << 3) + (lane & 7);
    const int khB = (lane >> 3) & 1;
    const int sxB = rB & 7;

    uint32_t rowOffA[4], rowOffB[2];
    #pragma unroll
    for (int mi = 0; mi < 4; mi++)
        rowOffA[mi] = (warp_m * 64 + mi * 16 + rA) * 128;
    #pragma unroll
    for (int p = 0; p < 2; p++)
        rowOffB[p] = OFF_B + (warp_n * 32 + p * 16 + rB) * 128;

    const int KT = K >> 5;  // chunks of 32

    ISSUE_CHUNK(0, 0);
    ISSUE_CHUNK(1, 1);

    int stage = 0;
    for (int kt = 0; kt < KT; kt++) {
        if (kt + 2 < KT) {
            int s2 = stage + 2; if (s2 >= 3) s2 -= 3;
            ISSUE_CHUNK(kt + 2, s2);
            cp_wait<2>();
        } else if (kt + 2 == KT) {
            cp_wait<1>();
        } else {
            cp_wait<0>();
        }
        __syncthreads();

        const uint32_t st = sbase + stage * STG;
        #pragma unroll
        for (int ks = 0; ks < 2; ks++) {
            const uint32_t uAh = (uint32_t)(((ks * 2 + khA) ^ sxA) << 4);
            const uint32_t uAl = (uint32_t)((((ks * 2 + khA) + 4) ^ sxA) << 4);
            const uint32_t uBh = (uint32_t)(((ks * 2 + khB) ^ sxB) << 4);
            const uint32_t uBl = (uint32_t)((((ks * 2 + khB) + 4) ^ sxB) << 4);

            uint4 bh0 = ldsm_x4(st + rowOffB[0] + uBh);
            uint4 bh1 = ldsm_x4(st + rowOffB[1] + uBh);
            uint4 bl0 = ldsm_x4(st + rowOffB[0] + uBl);
            uint4 bl1 = ldsm_x4(st + rowOffB[1] + uBl);

            #pragma unroll
            for (int mi = 0; mi < 4; mi++) {
                uint4 ah = ldsm_x4(st + rowOffA[mi] + uAh);
                uint4 al = ldsm_x4(st + rowOffA[mi] + uAl);
                mma_bf16(acc[mi][0], ah, bh0.x, bh0.y);
                mma_bf16(acc[mi][0], al, bh0.x, bh0.y);
                mma_bf16(acc[mi][0], ah, bl0.x, bl0.y);
                mma_bf16(acc[mi][1], ah, bh0.z, bh0.w);
                mma_bf16(acc[mi][1], al, bh0.z, bh0.w);
                mma_bf16(acc[mi][1], ah, bl0.z, bl0.w);
                mma_bf16(acc[mi][2], ah, bh1.x, bh1.y);
                mma_bf16(acc[mi][2], al, bh1.x, bh1.y);
                mma_bf16(acc[mi][2], ah, bl1.x, bl1.y);
                mma_bf16(acc[mi][3], ah, bh1.z, bh1.w);
                mma_bf16(acc[mi][3], al, bh1.z, bh1.w);
                mma_bf16(acc[mi][3], ah, bl1.z, bl1.w);
            }
        }
        __syncthreads();
        if (++stage == 3) stage = 0;
    }
#undef ISSUE_CHUNK

    // ---------------- epilogue ----------------
    const float theta = SOFT ? __ldg(thr) : 0.f;
    const int g = lane >> 2, tm = lane & 3;

    #pragma unroll
    for (int mi = 0; mi < 4; mi++) {
        #pragma unroll
        for (int half = 0; half < 2; half++) {
            const int row = by * 128 + warp_m * 64 + mi * 16 + g + half * 8;
            #pragma unroll
            for (int ni = 0; ni < 4; ni++) {
                const int col = bx * 128 + warp_n * 32 + ni * 8 + tm * 2;
                size_t off = (size_t)row * Ncols + col;
                float c0 = acc[mi][ni][half * 2 + 0];
                float c1 = acc[mi][ni][half * 2 + 1];
                if (ADD_V) {
                    float2 v = *(const float2*)(Vadd + off);
                    c0 += v.x;
                    c1 += v.y;
                }
                if (SOFT) {
                    c0 = soft_thr_f(c0, theta);
                    c1 = soft_thr_f(c1, theta);
                }
                if (WF32) *(float2*)(Cf + off) = make_float2(c0, c1);
                if (WSPLIT) {
                    __nv_bfloat16 h0 = __float2bfloat16(c0);
                    __nv_bfloat16 h1 = __float2bfloat16(c1);
                    __nv_bfloat16 l0 = __float2bfloat16(c0 - __bfloat162float(h0));
                    __nv_bfloat16 l1 = __float2bfloat16(c1 - __bfloat162float(h1));
                    *(__nv_bfloat162*)(Chi + off) = __nv_bfloat162(h0, h1);
                    *(__nv_bfloat162*)(Clo + off) = __nv_bfloat162(l0, l1);
                }
            }
        }
    }
}

// ---------------- launch ----------------------------------------------------
extern "C" void kernel_launch(void* const* d_in, const int* in_sizes, int n_in,
                              void* d_out, int out_size) {
    const float* y   = (const float*)d_in[0];  // (B, M)
    const float* S   = (const float*)d_in[1];  // (N, N)
    const float* W   = (const float*)d_in[2];  // (N, M)
    const float* D   = (const float*)d_in[3];  // (N, N)
    const float* thr = (const float*)d_in[4];  // (1, 1)
    float* out = (float*)d_out;                // (NITER+1, B, N)

    __nv_bfloat16 *yh, *yl, *Wh, *Wl, *Dh, *Dl, *Sth, *Stl, *Dth, *Dtl;
    __nv_bfloat16 *Eh, *El, *Wyh, *Wyl, *dh, *dl, *Ph, *Pl;
    float* Vf;
    cudaGetSymbolAddress((void**)&yh, g_yh);   cudaGetSymbolAddress((void**)&yl, g_yl);
    cudaGetSymbolAddress((void**)&Wh, g_Wh);   cudaGetSymbolAddress((void**)&Wl, g_Wl);
    cudaGetSymbolAddress((void**)&Dh, g_Dh);   cudaGetSymbolAddress((void**)&Dl, g_Dl);
    cudaGetSymbolAddress((void**)&Sth, g_Sth); cudaGetSymbolAddress((void**)&Stl, g_Stl);
    cudaGetSymbolAddress((void**)&Dth, g_Dth); cudaGetSymbolAddress((void**)&Dtl, g_Dtl);
    cudaGetSymbolAddress((void**)&Eh, g_Eh);   cudaGetSymbolAddress((void**)&El, g_El);
    cudaGetSymbolAddress((void**)&Wyh, g_Wyh); cudaGetSymbolAddress((void**)&Wyl, g_Wyl);
    cudaGetSymbolAddress((void**)&dh, g_dh);   cudaGetSymbolAddress((void**)&dl, g_dl);
    cudaGetSymbolAddress((void**)&Ph, g_Ph);   cudaGetSymbolAddress((void**)&Pl, g_Pl);
    cudaGetSymbolAddress((void**)&Vf, g_Vf);

    cudaFuncSetAttribute((const void*)gemm_tc<false, false, false, true>,
                         cudaFuncAttributeMaxDynamicSharedMemorySize, SMEM_TOTAL);
    cudaFuncSetAttribute((const void*)gemm_tc<false, false, true, false>,
                         cudaFuncAttributeMaxDynamicSharedMemorySize, SMEM_TOTAL);
    cudaFuncSetAttribute((const void*)gemm_tc<true, true, false, true>,
                         cudaFuncAttributeMaxDynamicSharedMemorySize, SMEM_TOTAL);
    cudaFuncSetAttribute((const void*)gemm_tc<false, false, true, true>,
                         cudaFuncAttributeMaxDynamicSharedMemorySize, SMEM_TOTAL);

    const size_t BN = (size_t)B_ * N_;
    dim3 tb(32, 8), tg(16, 16);
    dim3 gBig(N_ / 128, B_ / 128);   // (4, 64)
    dim3 gSmall(N_ / 128, N_ / 128); // (4, 4)

    // ---- prologue ----
    split_mat<<<(B_ * M_ / 4 + 255) / 256, 256>>>(y, yh, yl, B_ * M_);
    split_mat<<<(N_ * M_ / 4 + 255) / 256, 256>>>(W, Wh, Wl, N_ * M_);
    split_mat<<<(N_ * N_ / 4 + 255) / 256, 256>>>(D, Dh, Dl, N_ * N_);
    transpose_split512<<<tg, tb>>>(S, Sth, Stl);
    transpose_split512<<<tg, tb>>>(D, Dth, Dtl);

    // Wy = y @ W^T  (K = 256) -> split only
    gemm_tc<false, false, false, true><<<gBig, 256, SMEM_TOTAL>>>(
        yh, yl, Wh, Wl, nullptr, nullptr, Wyh, Wyl, M_, N_, nullptr);
    // E = D @ S = D @ St^T -> split only
    gemm_tc<false, false, false, true><<<gSmall, 256, SMEM_TOTAL>>>(
        Dh, Dl, Sth, Stl, nullptr, nullptr, Eh, El, N_, N_, nullptr);
    // V = Wy @ D^T -> fp32 only
    gemm_tc<false, false, true, false><<<gBig, 256, SMEM_TOTAL>>>(
        Wyh, Wyl, Dh, Dl, nullptr, Vf, nullptr, nullptr, N_, N_, nullptr);

    // d0 = 0 slot; P0 = soft_thr(V)
    cudaMemsetAsync(out, 0, BN * sizeof(float));
    thr_split<<<((int)BN / 4 + 255) / 256, 256>>>(Vf, Ph, Pl, thr, (int)BN);

    // Iterations (P_t already known):
    //   d_{t+1} = P_t @ Dt^T    -> out[t+1] fp32 (+ splits unless last)
    //   P_{t+1} = soft_thr(d_{t+1} @ E^T + V) -> splits
    for (int t = 0; t < NITER_; t++) {
        float* d_next = out + (size_t)(t + 1) * BN;
        if (t + 1 < NITER_) {
            gemm_tc<false, false, true, true><<<gBig, 256, SMEM_TOTAL>>>(
                Ph, Pl, Dth, Dtl, nullptr, d_next, dh, dl, N_, N_, nullptr);
            gemm_tc<true, true, false, true><<<gBig, 256, SMEM_TOTAL>>>(
                dh, dl, Eh, El, Vf, nullptr, Ph, Pl, N_, N_, thr);
        } else {
            gemm_tc<false, false, true, false><<<gBig, 256, SMEM_TOTAL>>>(
                Ph, Pl, Dth, Dtl, nullptr, d_next, nullptr, nullptr, N_, N_, nullptr);
        }
    }
}

// round 9
// speedup vs baseline: 1.0395x; 1.0395x over previous
#include <cuda_runtime.h>
#include <cuda_bf16.h>
#include <cstdint>

#define B_ 8192
#define M_ 256
#define N_ 512
#define NITER_ 16

// ---------------- device scratch (no allocation allowed) --------------------
__device__ __align__(128) __nv_bfloat16 g_yh[(size_t)B_ * M_], g_yl[(size_t)B_ * M_];
__device__ __align__(128) __nv_bfloat16 g_Wh[N_ * M_], g_Wl[N_ * M_];
__device__ __align__(128) __nv_bfloat16 g_Dh[N_ * N_], g_Dl[N_ * N_];
__device__ __align__(128) __nv_bfloat16 g_Sth[N_ * N_], g_Stl[N_ * N_];
__device__ __align__(128) __nv_bfloat16 g_Eh[N_ * N_], g_El[N_ * N_];
// Concatenated B for the fused iteration kernel: rows 0..511 = D^T, rows 512..1023 = F = E@D^T
__device__ __align__(128) __nv_bfloat16 g_Bch[2 * N_ * N_], g_Bcl[2 * N_ * N_];
__device__ __align__(128) __nv_bfloat16 g_Wyh[(size_t)B_ * N_], g_Wyl[(size_t)B_ * N_];
// Ping-pong P buffers
__device__ __align__(128) __nv_bfloat16 g_Pah[(size_t)B_ * N_], g_Pal[(size_t)B_ * N_];
__device__ __align__(128) __nv_bfloat16 g_Pbh[(size_t)B_ * N_], g_Pbl[(size_t)B_ * N_];
__device__ __align__(128) float g_Vf[(size_t)B_ * N_];

// ---------------- PTX helpers (compute_103 baseline ISA only) ---------------
__device__ __forceinline__ uint32_t smem_u32(const void* p) {
    uint32_t a;
    asm("{ .reg .u64 t; cvta.to.shared.u64 t, %1; cvt.u32.u64 %0, t; }"
        : "=r"(a) : "l"(p));
    return a;
}

__device__ __forceinline__ void cp16(uint32_t saddr, const void* gaddr) {
    asm volatile("cp.async.cg.shared.global [%0], [%1], 16;"
                 :: "r"(saddr), "l"(gaddr));
}
__device__ __forceinline__ void cp_commit() {
    asm volatile("cp.async.commit_group;");
}
template <int N>
__device__ __forceinline__ void cp_wait() {
    asm volatile("cp.async.wait_group %0;" :: "n"(N));
}

__device__ __forceinline__ uint4 ldsm_x4(uint32_t addr) {
    uint4 r;
    asm volatile("ldmatrix.sync.aligned.m8n8.x4.shared.b16 {%0,%1,%2,%3}, [%4];"
                 : "=r"(r.x), "=r"(r.y), "=r"(r.z), "=r"(r.w) : "r"(addr));
    return r;
}

__device__ __forceinline__ void mma_bf16(float* c, uint4 a, uint32_t b0, uint32_t b1) {
    asm volatile(
        "mma.sync.aligned.m16n8k16.row.col.f32.bf16.bf16.f32 "
        "{%0,%1,%2,%3}, {%4,%5,%6,%7}, {%8,%9}, {%0,%1,%2,%3};"
        : "+f"(c[0]), "+f"(c[1]), "+f"(c[2]), "+f"(c[3])
        : "r"(a.x), "r"(a.y), "r"(a.z), "r"(a.w), "r"(b0), "r"(b1));
}

__device__ __forceinline__ float soft_thr_f(float u, float t) {
    return fmaxf(u - t, 0.f) - fmaxf(-u - t, 0.f);
}

// ---------------- prologue / elementwise kernels ----------------------------
__global__ void split_mat(const float* __restrict__ in,
                          __nv_bfloat16* __restrict__ hi,
                          __nv_bfloat16* __restrict__ lo, int n) {
    int i = (blockIdx.x * blockDim.x + threadIdx.x) * 4;
    if (i >= n) return;
    float4 v = *(const float4*)(in + i);
    float x[4] = {v.x, v.y, v.z, v.w};
    __nv_bfloat16 h[4], l[4];
    #pragma unroll
    for (int j = 0; j < 4; j++) {
        h[j] = __float2bfloat16(x[j]);
        l[j] = __float2bfloat16(x[j] - __bfloat162float(h[j]));
    }
    *(__nv_bfloat162*)(hi + i)     = __nv_bfloat162(h[0], h[1]);
    *(__nv_bfloat162*)(hi + i + 2) = __nv_bfloat162(h[2], h[3]);
    *(__nv_bfloat162*)(lo + i)     = __nv_bfloat162(l[0], l[1]);
    *(__nv_bfloat162*)(lo + i + 2) = __nv_bfloat162(l[2], l[3]);
}

// P0 = soft_thr(V) split  (d0 = 0 makes the first step trivial)
__global__ void thr_split(const float* __restrict__ V,
                          __nv_bfloat16* __restrict__ hi,
                          __nv_bfloat16* __restrict__ lo,
                          const float* __restrict__ thr, int n) {
    int i = (blockIdx.x * blockDim.x + threadIdx.x) * 4;
    if (i >= n) return;
    float theta = __ldg(thr);
    float4 v = *(const float4*)(V + i);
    float x[4] = {v.x, v.y, v.z, v.w};
    __nv_bfloat16 h[4], l[4];
    #pragma unroll
    for (int j = 0; j < 4; j++) {
        float a = soft_thr_f(x[j], theta);
        h[j] = __float2bfloat16(a);
        l[j] = __float2bfloat16(a - __bfloat162float(h[j]));
    }
    *(__nv_bfloat162*)(hi + i)     = __nv_bfloat162(h[0], h[1]);
    *(__nv_bfloat162*)(hi + i + 2) = __nv_bfloat162(h[2], h[3]);
    *(__nv_bfloat162*)(lo + i)     = __nv_bfloat162(l[0], l[1]);
    *(__nv_bfloat162*)(lo + i + 2) = __nv_bfloat162(l[2], l[3]);
}

// out = in^T for 512x512, emitting bf16 hi/lo split
__global__ void transpose_split512(const float* __restrict__ in,
                                   __nv_bfloat16* __restrict__ hi,
                                   __nv_bfloat16* __restrict__ lo) {
    __shared__ float tile[32][33];
    int x = blockIdx.x * 32 + threadIdx.x;
    int y0 = blockIdx.y * 32;
    #pragma unroll
    for (int j = threadIdx.y; j < 32; j += 8)
        tile[j][threadIdx.x] = in[(size_t)(y0 + j) * N_ + x];
    __syncthreads();
    int xo = blockIdx.y * 32 + threadIdx.x;
    int yo0 = blockIdx.x * 32;
    #pragma unroll
    for (int j = threadIdx.y; j < 32; j += 8) {
        float v = tile[threadIdx.x][j];
        __nv_bfloat16 h = __float2bfloat16(v);
        __nv_bfloat16 l = __float2bfloat16(v - __bfloat162float(h));
        size_t o = (size_t)(yo0 + j) * N_ + xo;
        hi[o] = h;
        lo[o] = l;
    }
}

// ---------------- shared split-bf16 mainloop (mma.sync) ---------------------
// Computes 128x128 CTA tile of A @ Bm^T (3-term split emulation) into acc.
// SMEM: per stage 64KB = A region (AH 16KB + AL 16KB) + B region (BH + BL).
// 3 stages = 192KB, 1 CTA/SM. K-chunk 64.
static constexpr int OFF_AH = 0;
static constexpr int OFF_AL = 16384;
static constexpr int OFF_BH = 32768;
static constexpr int OFF_BL = 49152;
static constexpr int STG = 65536;
static constexpr int SMEM_TOTAL = 3 * STG;  // 196608

__device__ __forceinline__ void issue_chunk(
    uint32_t stb, const __nv_bfloat16* __restrict__ Ah, const __nv_bfloat16* __restrict__ Al,
    const __nv_bfloat16* __restrict__ Bh, const __nv_bfloat16* __restrict__ Bl,
    int rowA0, int rowB0, int K, int kt, int tid) {
    #pragma unroll
    for (int i = 0; i < 4; i++) {
        int unit = tid + 256 * i;
        int row = unit >> 3, u = unit & 7;
        uint32_t so = (uint32_t)(row * 128 + ((u ^ (row & 7)) << 4));
        size_t goA = (size_t)(rowA0 + row) * K + kt * 64 + u * 8;
        size_t goB = (size_t)(rowB0 + row) * K + kt * 64 + u * 8;
        cp16(stb + OFF_AH + so, Ah + goA);
        cp16(stb + OFF_AL + so, Al + goA);
        cp16(stb + OFF_BH + so, Bh + goB);
        cp16(stb + OFF_BL + so, Bl + goB);
    }
    cp_commit();
}

__device__ __forceinline__ void mainloop_128x128(
    const __nv_bfloat16* __restrict__ Ah, const __nv_bfloat16* __restrict__ Al,
    const __nv_bfloat16* __restrict__ Bh, const __nv_bfloat16* __restrict__ Bl,
    int K, int rowA0, int rowB0, uint32_t sbase, int tid,
    float acc[4][4][4]) {
    const int lane = tid & 31;
    const int wid = tid >> 5;
    const int warp_m = wid & 1;
    const int warp_n = wid >> 1;

    const int rA = lane & 15;
    const int khA = lane >> 4;
    const int sxA = rA & 7;
    const int rB = ((lane >> 4) << 3) + (lane & 7);
    const int khB = (lane >> 3) & 1;
    const int sxB = rB & 7;

    uint32_t rowOffA[4], rowOffB[2];
    #pragma unroll
    for (int mi = 0; mi < 4; mi++)
        rowOffA[mi] = (warp_m * 64 + mi * 16 + rA) * 128;
    #pragma unroll
    for (int p = 0; p < 2; p++)
        rowOffB[p] = (warp_n * 32 + p * 16 + rB) * 128;

    const int KT = K >> 6;

    issue_chunk(sbase, Ah, Al, Bh, Bl, rowA0, rowB0, K, 0, tid);
    if (KT > 1) issue_chunk(sbase + STG, Ah, Al, Bh, Bl, rowA0, rowB0, K, 1, tid);

    int stage = 0;
    for (int kt = 0; kt < KT; kt++) {
        if (kt + 2 < KT) {
            int s2 = stage + 2; if (s2 >= 3) s2 -= 3;
            issue_chunk(sbase + s2 * STG, Ah, Al, Bh, Bl, rowA0, rowB0, K, kt + 2, tid);
            cp_wait<2>();
        } else if (kt + 2 == KT) {
            cp_wait<1>();
        } else {
            cp_wait<0>();
        }
        __syncthreads();

        const uint32_t st = sbase + stage * STG;
        #pragma unroll
        for (int ks = 0; ks < 4; ks++) {
            const uint32_t uA = (uint32_t)(((ks * 2 + khA) ^ sxA) << 4);
            const uint32_t uB = (uint32_t)(((ks * 2 + khB) ^ sxB) << 4);

            uint4 bh0 = ldsm_x4(st + OFF_BH + rowOffB[0] + uB);
            uint4 bh1 = ldsm_x4(st + OFF_BH + rowOffB[1] + uB);
            uint4 bl0 = ldsm_x4(st + OFF_BL + rowOffB[0] + uB);
            uint4 bl1 = ldsm_x4(st + OFF_BL + rowOffB[1] + uB);

            #pragma unroll
            for (int mi = 0; mi < 4; mi++) {
                uint4 ah = ldsm_x4(st + OFF_AH + rowOffA[mi] + uA);
                uint4 al = ldsm_x4(st + OFF_AL + rowOffA[mi] + uA);
                mma_bf16(acc[mi][0], ah, bh0.x, bh0.y);
                mma_bf16(acc[mi][0], al, bh0.x, bh0.y);
                mma_bf16(acc[mi][0], ah, bl0.x, bl0.y);
                mma_bf16(acc[mi][1], ah, bh0.z, bh0.w);
                mma_bf16(acc[mi][1], al, bh0.z, bh0.w);
                mma_bf16(acc[mi][1], ah, bl0.z, bl0.w);
                mma_bf16(acc[mi][2], ah, bh1.x, bh1.y);
                mma_bf16(acc[mi][2], al, bh1.x, bh1.y);
                mma_bf16(acc[mi][2], ah, bl1.x, bl1.y);
                mma_bf16(acc[mi][3], ah, bh1.z, bh1.w);
                mma_bf16(acc[mi][3], al, bh1.z, bh1.w);
                mma_bf16(acc[mi][3], ah, bl1.z, bl1.w);
            }
        }
        __syncthreads();
        if (++stage == 3) stage = 0;
    }
}

// ---------------- generic GEMM (prologue) -----------------------------------
template <bool WF32, bool WSPLIT>
__global__ __launch_bounds__(256, 1)
void gemm_tc(const __nv_bfloat16* __restrict__ Ah, const __nv_bfloat16* __restrict__ Al,
             const __nv_bfloat16* __restrict__ Bh, const __nv_bfloat16* __restrict__ Bl,
             float* __restrict__ Cf,
             __nv_bfloat16* __restrict__ Chi, __nv_bfloat16* __restrict__ Clo,
             int K) {
    extern __shared__ char sm[];
    const uint32_t sbase = smem_u32(sm);
    const int tid = threadIdx.x;
    const int lane = tid & 31;
    const int wid = tid >> 5;
    const int warp_m = wid & 1;
    const int warp_n = wid >> 1;

    float acc[4][4][4];
    #pragma unroll
    for (int a = 0; a < 4; a++)
        #pragma unroll
        for (int b = 0; b < 4; b++)
            #pragma unroll
            for (int c = 0; c < 4; c++) acc[a][b][c] = 0.f;

    mainloop_128x128(Ah, Al, Bh, Bl, K, blockIdx.y * 128, blockIdx.x * 128,
                     sbase, tid, acc);

    const int g = lane >> 2, tm = lane & 3;
    #pragma unroll
    for (int mi = 0; mi < 4; mi++) {
        #pragma unroll
        for (int half = 0; half < 2; half++) {
            const int row = blockIdx.y * 128 + warp_m * 64 + mi * 16 + g + half * 8;
            #pragma unroll
            for (int ni = 0; ni < 4; ni++) {
                const int col = blockIdx.x * 128 + warp_n * 32 + ni * 8 + tm * 2;
                size_t off = (size_t)row * N_ + col;
                float c0 = acc[mi][ni][half * 2 + 0];
                float c1 = acc[mi][ni][half * 2 + 1];
                if (WF32) *(float2*)(Cf + off) = make_float2(c0, c1);
                if (WSPLIT) {
                    __nv_bfloat16 h0 = __float2bfloat16(c0);
                    __nv_bfloat16 h1 = __float2bfloat16(c1);
                    __nv_bfloat16 l0 = __float2bfloat16(c0 - __bfloat162float(h0));
                    __nv_bfloat16 l1 = __float2bfloat16(c1 - __bfloat162float(h1));
                    *(__nv_bfloat162*)(Chi + off) = __nv_bfloat162(h0, h1);
                    *(__nv_bfloat162*)(Clo + off) = __nv_bfloat162(l0, l1);
                }
            }
        }
    }
}

// ---------------- fused iteration GEMM --------------------------------------
// Grid (8, 64): bx 0..3 -> d_{t+1} = P @ Dt^T (fp32 to out slot)
//               bx 4..7 -> P_{t+1} = soft_thr(P @ F^T + V) (split to Pn)
// B operand = concatenated [Dt | F] (1024 x 512).
__global__ __launch_bounds__(256, 1)
void gemm_fused(const __nv_bfloat16* __restrict__ Ph, const __nv_bfloat16* __restrict__ Pl,
                const __nv_bfloat16* __restrict__ Bch, const __nv_bfloat16* __restrict__ Bcl,
                const float* __restrict__ Vf, float* __restrict__ outSlot,
                __nv_bfloat16* __restrict__ Pnh, __nv_bfloat16* __restrict__ Pnl,
                const float* __restrict__ thr) {
    extern __shared__ char sm[];
    const uint32_t sbase = smem_u32(sm);
    const int tid = threadIdx.x;
    const int lane = tid & 31;
    const int wid = tid >> 5;
    const int warp_m = wid & 1;
    const int warp_n = wid >> 1;
    const int bx = blockIdx.x, by = blockIdx.y;

    float acc[4][4][4];
    #pragma unroll
    for (int a = 0; a < 4; a++)
        #pragma unroll
        for (int b = 0; b < 4; b++)
            #pragma unroll
            for (int c = 0; c < 4; c++) acc[a][b][c] = 0.f;

    mainloop_128x128(Ph, Pl, Bch, Bcl, N_, by * 128, bx * 128, sbase, tid, acc);

    const bool isP = bx >= 4;
    const int colbase = (bx & 3) * 128;
    const float theta = __ldg(thr);
    const int g = lane >> 2, tm = lane & 3;

    #pragma unroll
    for (int mi = 0; mi < 4; mi++) {
        #pragma unroll
        for (int half = 0; half < 2; half++) {
            const int row = by * 128 + warp_m * 64 + mi * 16 + g + half * 8;
            #pragma unroll
            for (int ni = 0; ni < 4; ni++) {
                const int col = colbase + warp_n * 32 + ni * 8 + tm * 2;
                size_t off = (size_t)row * N_ + col;
                float c0 = acc[mi][ni][half * 2 + 0];
                float c1 = acc[mi][ni][half * 2 + 1];
                if (!isP) {
                    *(float2*)(outSlot + off) = make_float2(c0, c1);
                } else {
                    float2 v = *(const float2*)(Vf + off);
                    c0 = soft_thr_f(c0 + v.x, theta);
                    c1 = soft_thr_f(c1 + v.y, theta);
                    __nv_bfloat16 h0 = __float2bfloat16(c0);
                    __nv_bfloat16 h1 = __float2bfloat16(c1);
                    __nv_bfloat16 l0 = __float2bfloat16(c0 - __bfloat162float(h0));
                    __nv_bfloat16 l1 = __float2bfloat16(c1 - __bfloat162float(h1));
                    *(__nv_bfloat162*)(Pnh + off) = __nv_bfloat162(h0, h1);
                    *(__nv_bfloat162*)(Pnl + off) = __nv_bfloat162(l0, l1);
                }
            }
        }
    }
}

// ---------------- launch ----------------------------------------------------
extern "C" void kernel_launch(void* const* d_in, const int* in_sizes, int n_in,
                              void* d_out, int out_size) {
    const float* y   = (const float*)d_in[0];  // (B, M)
    const float* S   = (const float*)d_in[1];  // (N, N)
    const float* W   = (const float*)d_in[2];  // (N, M)
    const float* D   = (const float*)d_in[3];  // (N, N)
    const float* thr = (const float*)d_in[4];  // (1, 1)
    float* out = (float*)d_out;                // (NITER+1, B, N)

    __nv_bfloat16 *yh, *yl, *Wh, *Wl, *Dh, *Dl, *Sth, *Stl, *Eh, *El;
    __nv_bfloat16 *Bch, *Bcl, *Wyh, *Wyl, *Pah, *Pal, *Pbh, *Pbl;
    float* Vf;
    cudaGetSymbolAddress((void**)&yh, g_yh);   cudaGetSymbolAddress((void**)&yl, g_yl);
    cudaGetSymbolAddress((void**)&Wh, g_Wh);   cudaGetSymbolAddress((void**)&Wl, g_Wl);
    cudaGetSymbolAddress((void**)&Dh, g_Dh);   cudaGetSymbolAddress((void**)&Dl, g_Dl);
    cudaGetSymbolAddress((void**)&Sth, g_Sth); cudaGetSymbolAddress((void**)&Stl, g_Stl);
    cudaGetSymbolAddress((void**)&Eh, g_Eh);   cudaGetSymbolAddress((void**)&El, g_El);
    cudaGetSymbolAddress((void**)&Bch, g_Bch); cudaGetSymbolAddress((void**)&Bcl, g_Bcl);
    cudaGetSymbolAddress((void**)&Wyh, g_Wyh); cudaGetSymbolAddress((void**)&Wyl, g_Wyl);
    cudaGetSymbolAddress((void**)&Pah, g_Pah); cudaGetSymbolAddress((void**)&Pal, g_Pal);
    cudaGetSymbolAddress((void**)&Pbh, g_Pbh); cudaGetSymbolAddress((void**)&Pbl, g_Pbl);
    cudaGetSymbolAddress((void**)&Vf, g_Vf);

    cudaFuncSetAttribute((const void*)gemm_tc<false, true>,
                         cudaFuncAttributeMaxDynamicSharedMemorySize, SMEM_TOTAL);
    cudaFuncSetAttribute((const void*)gemm_tc<true, false>,
                         cudaFuncAttributeMaxDynamicSharedMemorySize, SMEM_TOTAL);
    cudaFuncSetAttribute((const void*)gemm_fused,
                         cudaFuncAttributeMaxDynamicSharedMemorySize, SMEM_TOTAL);

    const size_t BN = (size_t)B_ * N_;
    dim3 tb(32, 8), tg(16, 16);
    dim3 gBig(N_ / 128, B_ / 128);   // (4, 64)
    dim3 gSmall(N_ / 128, N_ / 128); // (4, 4)
    dim3 gFull(8, B_ / 128);         // (8, 64)

    // ---- prologue ----
    split_mat<<<(B_ * M_ / 4 + 255) / 256, 256>>>(y, yh, yl, B_ * M_);
    split_mat<<<(N_ * M_ / 4 + 255) / 256, 256>>>(W, Wh, Wl, N_ * M_);
    split_mat<<<(N_ * N_ / 4 + 255) / 256, 256>>>(D, Dh, Dl, N_ * N_);
    transpose_split512<<<tg, tb>>>(S, Sth, Stl);          // S^T split
    transpose_split512<<<tg, tb>>>(D, Bch, Bcl);          // D^T -> Bcat rows 0..511

    // Wy = y @ W^T (K=256) -> split
    gemm_tc<false, true><<<gBig, 256, SMEM_TOTAL>>>(
        yh, yl, Wh, Wl, nullptr, Wyh, Wyl, M_);
    // E = D @ S = D @ St^T -> split
    gemm_tc<false, true><<<gSmall, 256, SMEM_TOTAL>>>(
        Dh, Dl, Sth, Stl, nullptr, Eh, El, N_);
    // V = Wy @ D^T -> fp32
    gemm_tc<true, false><<<gBig, 256, SMEM_TOTAL>>>(
        Wyh, Wyl, Dh, Dl, Vf, nullptr, nullptr, N_);
    // F = E @ D^T -> split into Bcat rows 512..1023
    gemm_tc<false, true><<<gSmall, 256, SMEM_TOTAL>>>(
        Eh, El, Dh, Dl, nullptr, Bch + (size_t)N_ * N_, Bcl + (size_t)N_ * N_, N_);

    // d0 = 0 slot; P0 = soft_thr(V)
    cudaMemsetAsync(out, 0, BN * sizeof(float));
    thr_split<<<((int)BN / 4 + 255) / 256, 256>>>(Vf, Pah, Pal, thr, (int)BN);

    // Iterations: launch t reads P_t, writes out[t+1] (=P_t@Dt^T) and
    // P_{t+1} = soft_thr(P_t@F^T + V). Last launch: d-half only (grid 4x64).
    for (int t = 0; t < NITER_; t++) {
        float* d_next = out + (size_t)(t + 1) * BN;
        const __nv_bfloat16* Ah = (t & 1) ? Pbh : Pah;
        const __nv_bfloat16* Al = (t & 1) ? Pbl : Pal;
        __nv_bfloat16* Pnh = (t & 1) ? Pah : Pbh;
        __nv_bfloat16* Pnl = (t & 1) ? Pal : Pbl;
        if (t + 1 < NITER_) {
            gemm_fused<<<gFull, 256, SMEM_TOTAL>>>(
                Ah, Al, Bch, Bcl, Vf, d_next, Pnh, Pnl, thr);
        } else {
            gemm_fused<<<gBig, 256, SMEM_TOTAL>>>(
                Ah, Al, Bch, Bcl, Vf, d_next, Pnh, Pnl, thr);
        }
    }
}